// round 15
// baseline (speedup 1.0000x reference)
#include <cuda_runtime.h>
#include <cuda_bf16.h>
#include <cstdint>

// ===========================================================================
// MTLoRALinear on sm_103a — single-pass tf32 mainloop, BK=64 (R15).
// R14 (512.7us) + lora_y persistent 2-tile blocks (128 blocks x 2 m-tiles:
// one full wave on 148 SMs instead of 2 ragged waves).
//   prep_wt : W fp32 -> tf32-rounded fp32
//   lora_y  : Y[M,80] = x @ concat(A_sh,A_tasks)^T (tf32) AND x -> g_xt
//   fused   : P = x@W^T single tf32 pass, BM128 BN256 BK64; epilogue: bias +
//             5 rank-16 tf32 corrections + streamed stores.
// ===========================================================================

namespace {
constexpr int MTOT = 32768, DK = 1024, OK = 1024;
constexpr int BM = 128, BN = 256, BK = 64;
constexpr int NCHUNK = DK / BK;           // 16
constexpr int NSTAGE = 2;
// stage layout (256B rows of 64 f32): x(32K) w(64K) = 96KB
constexpr int OFF_X = 0, OFF_W = 32768;
constexpr int STAGE_B = 98304;
constexpr int SMEM_DYN = NSTAGE * STAGE_B + 1024;   // 197632
constexpr int XST = 36;                   // lora_y smem stride
constexpr int EST = 84;                   // epilogue stride (conflict-free)
constexpr int EPI_B_OFF = 43520;          // Ys: 128*84*4=43008, Bs after
}

__device__ __align__(256) float g_xt[MTOT * DK];   // tf32-rounded x
__device__ __align__(256) float g_wt[OK * DK];     // tf32-rounded W
__device__ __align__(256) float g_Y[MTOT * 80];

// --------------------------- helpers ---------------------------------------
__device__ __forceinline__ uint32_t smem_u32(const void* p) {
    uint32_t a;
    asm("{ .reg .u64 t; cvta.to.shared.u64 t, %1; cvt.u32.u64 %0, t; }"
        : "=r"(a) : "l"(p));
    return a;
}
__device__ __forceinline__ void cp16(uint32_t dst, const void* src) {
    asm volatile("cp.async.cg.shared.global [%0], [%1], 16;"
                 :: "r"(dst), "l"(src) : "memory");
}
__device__ __forceinline__ void cp_commit() {
    asm volatile("cp.async.commit_group;" ::: "memory");
}
template <int N> __device__ __forceinline__ void cp_wait() {
    asm volatile("cp.async.wait_group %0;" :: "n"(N) : "memory");
}
__device__ __forceinline__ void ldsm4(uint32_t& r0, uint32_t& r1, uint32_t& r2,
                                      uint32_t& r3, uint32_t a) {
    asm volatile("ldmatrix.sync.aligned.m8n8.x4.shared.b16 {%0,%1,%2,%3}, [%4];"
                 : "=r"(r0), "=r"(r1), "=r"(r2), "=r"(r3) : "r"(a));
}
__device__ __forceinline__ uint32_t tf32_rna(float x) {
    uint32_t u;
    asm("cvt.rna.tf32.f32 %0, %1;" : "=r"(u) : "f"(x));
    return u;
}
__device__ __forceinline__ float tf32f(float x) {
    return __uint_as_float(tf32_rna(x));
}
__device__ __forceinline__ void mma_tf32(float* c, const uint32_t* a,
                                         const uint32_t* b) {
    asm volatile(
        "mma.sync.aligned.m16n8k8.row.col.f32.tf32.tf32.f32 "
        "{%0,%1,%2,%3}, {%4,%5,%6,%7}, {%8,%9}, {%0,%1,%2,%3};"
        : "+f"(c[0]), "+f"(c[1]), "+f"(c[2]), "+f"(c[3])
        : "r"(a[0]), "r"(a[1]), "r"(a[2]), "r"(a[3]), "r"(b[0]), "r"(b[1]));
}
__device__ __forceinline__ void mma_tf32_dc(float* d, const float* c,
                                            const uint32_t* a, const uint32_t* b) {
    asm volatile(
        "mma.sync.aligned.m16n8k8.row.col.f32.tf32.tf32.f32 "
        "{%0,%1,%2,%3}, {%4,%5,%6,%7}, {%8,%9}, {%10,%11,%12,%13};"
        : "=f"(d[0]), "=f"(d[1]), "=f"(d[2]), "=f"(d[3])
        : "r"(a[0]), "r"(a[1]), "r"(a[2]), "r"(a[3]), "r"(b[0]), "r"(b[1]),
          "f"(c[0]), "f"(c[1]), "f"(c[2]), "f"(c[3]));
}
// 256B-row tile (64 f32), 16x16B chunks, XOR-8 swizzle (R14-proven).
__device__ __forceinline__ uint32_t tswz128(int row, int ch) {
    return (uint32_t)(row * 256 + ((ch ^ (row & 7)) << 4));
}

// --------------------------- prep W (tf32 round) ---------------------------
__global__ __launch_bounds__(256) void prep_wt(const float* __restrict__ W) {
    size_t i = ((size_t)blockIdx.x * 256 + threadIdx.x) * 4;
    float4 v = *reinterpret_cast<const float4*>(W + i);
    v.x = tf32f(v.x); v.y = tf32f(v.y); v.z = tf32f(v.z); v.w = tf32f(v.w);
    *reinterpret_cast<float4*>(g_wt + i) = v;
}

// ---------------- lora_y: persistent 2-tile blocks -------------------------
__global__ __launch_bounds__(256) void lora_y_kernel(
    const float* __restrict__ x,
    const float* __restrict__ A_sh,
    const float* __restrict__ A_tasks)
{
    __shared__ float Xs[BM * XST];
    __shared__ float Ws[BM * XST];

    const int tid = threadIdx.x;
    const int lane = tid & 31, wid = tid >> 5;
    const int wm = wid >> 2, wn = wid & 3;
    const int lr = tid >> 3;
    const int lc = (tid & 7) << 2;

    // A pointers are m-tile independent: derive once
    const float* ag[4];
    bool av[4];
#pragma unroll
    for (int i = 0; i < 4; i++) {
        const int r = lr + 32 * i;
        if (r < 16)      { ag[i] = A_sh + (size_t)r * DK + lc; av[i] = true; }
        else if (r < 80) { ag[i] = A_tasks + (size_t)(r - 16) * DK + lc; av[i] = true; }
        else             { ag[i] = A_sh + lc; av[i] = false; }
    }
    const float4 z4 = make_float4(0.f, 0.f, 0.f, 0.f);

    for (int t = 0; t < 2; t++) {
        const int m0 = (blockIdx.x + t * 128) * BM;
        const float* xg = x + (size_t)(m0 + lr) * DK + lc;

        float4 px[4], pw[4];
#pragma unroll
        for (int i = 0; i < 4; i++) {
            px[i] = *reinterpret_cast<const float4*>(xg + (size_t)(32 * i) * DK);
            pw[i] = av[i] ? *reinterpret_cast<const float4*>(ag[i]) : z4;
        }

        float c[4][4][4];
#pragma unroll
        for (int i = 0; i < 4; i++)
#pragma unroll
            for (int j = 0; j < 4; j++)
#pragma unroll
                for (int q = 0; q < 4; q++) c[i][j][q] = 0.f;

        for (int kc = 0; kc < DK; kc += 32) {
            __syncthreads();
#pragma unroll
            for (int i = 0; i < 4; i++) {
                float4 xr = make_float4(tf32f(px[i].x), tf32f(px[i].y),
                                        tf32f(px[i].z), tf32f(px[i].w));
                *reinterpret_cast<float4*>(
                    g_xt + (size_t)(m0 + lr + 32 * i) * DK + kc + lc) = xr;
                float* xs = &Xs[(lr + 32 * i) * XST + lc];
                xs[0] = xr.x; xs[1] = xr.y; xs[2] = xr.z; xs[3] = xr.w;
                float* ws = &Ws[(lr + 32 * i) * XST + lc];
                ws[0] = tf32f(pw[i].x); ws[1] = tf32f(pw[i].y);
                ws[2] = tf32f(pw[i].z); ws[3] = tf32f(pw[i].w);
            }
            __syncthreads();
            if (kc + 32 < DK) {
#pragma unroll
                for (int i = 0; i < 4; i++) {
                    px[i] = *reinterpret_cast<const float4*>(
                        xg + (size_t)(32 * i) * DK + kc + 32);
                    pw[i] = av[i] ? *reinterpret_cast<const float4*>(ag[i] + kc + 32)
                                  : z4;
                }
            }
#pragma unroll
            for (int ks = 0; ks < 4; ks++) {
                const int ak = ks * 8 + (lane & 3);
                const int ar = wm * 64 + (lane >> 2);
                uint32_t a[4][4];
#pragma unroll
                for (int i = 0; i < 4; i++) {
                    const float* base = &Xs[(ar + i * 16) * XST + ak];
                    a[i][0] = __float_as_uint(base[0]);
                    a[i][1] = __float_as_uint(base[8 * XST]);
                    a[i][2] = __float_as_uint(base[4]);
                    a[i][3] = __float_as_uint(base[8 * XST + 4]);
                }
                uint32_t b[4][2];
                const int bn = wn * 32 + (lane >> 2);
#pragma unroll
                for (int j = 0; j < 4; j++) {
                    const float* base = &Ws[(bn + j * 8) * XST + ak];
                    b[j][0] = __float_as_uint(base[0]);
                    b[j][1] = __float_as_uint(base[4]);
                }
#pragma unroll
                for (int i = 0; i < 4; i++)
#pragma unroll
                    for (int j = 0; j < 4; j++)
                        mma_tf32(c[i][j], a[i], b[j]);
            }
        }

#pragma unroll
        for (int j = 0; j < 4; j++) {
            const int colb = wn * 32 + j * 8 + (lane & 3) * 2;
            if (colb < 80) {
#pragma unroll
                for (int i = 0; i < 4; i++) {
                    const int r0 = m0 + wm * 64 + i * 16 + (lane >> 2);
                    *reinterpret_cast<float2*>(g_Y + (size_t)r0 * 80 + colb) =
                        make_float2(c[i][j][0], c[i][j][1]);
                    *reinterpret_cast<float2*>(g_Y + (size_t)(r0 + 8) * 80 + colb) =
                        make_float2(c[i][j][2], c[i][j][3]);
                }
            }
        }
        __syncthreads();   // smem reuse across tiles
    }
}

// --------------------------- fused main ------------------------------------
__global__ __launch_bounds__(256, 1) void fused_main(
    const float* __restrict__ bias,
    const float* __restrict__ B_sh,
    const float* __restrict__ B_tasks,
    const float* __restrict__ task_scales,
    float* __restrict__ out)
{
    extern __shared__ char dsm[];
    const uint32_t raw = smem_u32(dsm);
    const uint32_t base = (raw + 1023u) & ~1023u;
    char* sm = dsm + (base - raw);

    const int tid = threadIdx.x, wid = tid >> 5, lane = tid & 31;
    const int wm = wid >> 2, wn = wid & 3;      // 2 x 4 warps, warp tile 64x64
    const int m0 = blockIdx.y * BM, n0 = blockIdx.x * BN;

    const int trow = tid >> 3, tch = tid & 7;
    const uint32_t dsw0 = tswz128(trow, tch);
    const uint32_t dsw1 = tswz128(trow, tch + 8);
    const float* xp = g_xt + (size_t)(m0 + trow) * DK + tch * 4;
    const float* wp = g_wt + (size_t)(n0 + trow) * DK + tch * 4;

    auto issue = [&](int chunk) {
        const uint32_t sb = base + (chunk & (NSTAGE - 1)) * STAGE_B;
        const int ko = chunk * BK;
#pragma unroll
        for (int p = 0; p < 4; p++) {
            const float* s = xp + (size_t)p * 32 * DK + ko;
            cp16(sb + OFF_X + p * 8192 + dsw0, s);
            cp16(sb + OFF_X + p * 8192 + dsw1, s + 32);
        }
#pragma unroll
        for (int p = 0; p < 8; p++) {
            const float* s = wp + (size_t)p * 32 * DK + ko;
            cp16(sb + OFF_W + p * 8192 + dsw0, s);
            cp16(sb + OFF_W + p * 8192 + dsw1, s + 32);
        }
        cp_commit();
    };

    issue(0);

    float c[8][4][4];
#pragma unroll
    for (int j = 0; j < 8; j++)
#pragma unroll
        for (int i = 0; i < 4; i++)
#pragma unroll
            for (int q = 0; q < 4; q++) c[j][i][q] = 0.f;

    const int qrow = lane & 7, q = lane >> 3;
    const int a_row_off = wm * 64 + (q & 1) * 8 + qrow;       // + i*16
    const int a_ch_off = q >> 1;                              // + ks*2
    const int b_row_off = wn * 64 + ((lane >> 4) << 3) + (lane & 7);  // + jp*16
    const int b_ch_off = (lane >> 3) & 1;                     // + ks*2

    for (int it = 0; it < NCHUNK; it++) {
        cp_wait<0>();
        __syncthreads();
        if (it + 1 < NCHUNK) issue(it + 1);   // overlaps all of compute(it)
        const uint32_t sb = base + (it & (NSTAGE - 1)) * STAGE_B;
#pragma unroll
        for (int ks = 0; ks < 8; ks++) {      // 8 k8-steps per 64-K chunk
            uint32_t a[4][4];
#pragma unroll
            for (int i = 0; i < 4; i++) {
                const int row = a_row_off + i * 16;
                const uint32_t o = tswz128(row, ks * 2 + a_ch_off);
                ldsm4(a[i][0], a[i][1], a[i][2], a[i][3], sb + OFF_X + o);
            }
#pragma unroll
            for (int jp = 0; jp < 4; jp++) {
                const int row = b_row_off + jp * 16;
                const uint32_t o = tswz128(row, ks * 2 + b_ch_off);
                uint32_t b[4];
                ldsm4(b[0], b[1], b[2], b[3], sb + OFF_W + o);
#pragma unroll
                for (int jj = 0; jj < 2; jj++)
#pragma unroll
                    for (int i = 0; i < 4; i++)
                        mma_tf32(c[jp * 2 + jj][i], a[i], b + 2 * jj);
            }
        }
    }
    __syncthreads();

    // ---- bias ------------------------------------------------------------
#pragma unroll
    for (int j = 0; j < 8; j++) {
        const int col = n0 + wn * 64 + j * 8 + (lane & 3) * 2;
        const float b0 = __ldg(bias + col);
        const float b1 = __ldg(bias + col + 1);
#pragma unroll
        for (int i = 0; i < 4; i++) {
            c[j][i][0] += b0; c[j][i][1] += b1;
            c[j][i][2] += b0; c[j][i][3] += b1;
        }
    }

    // ---- epilogue: stage Y[128x80] and scaled B_all[256x80] once ----------
    float* Ys = reinterpret_cast<float*>(sm);
    float* Bs = reinterpret_cast<float*>(sm + EPI_B_OFF);
    {
        const int srow = tid >> 1, half = tid & 1;
        const float* ys = g_Y + (size_t)(m0 + srow) * 80 + half * 40;
        float* yd = Ys + srow * EST + half * 40;
#pragma unroll
        for (int g = 0; g < 10; g++) {
            float4 v = __ldg(reinterpret_cast<const float4*>(ys + g * 4));
            yd[g * 4 + 0] = tf32f(v.x); yd[g * 4 + 1] = tf32f(v.y);
            yd[g * 4 + 2] = tf32f(v.z); yd[g * 4 + 3] = tf32f(v.w);
        }
        float sc[4];
#pragma unroll
        for (int t = 0; t < 4; t++) sc[t] = __ldg(task_scales + t);
        float* bd = Bs + tid * EST;
#pragma unroll
        for (int g = 0; g < 20; g++) {
            const int k0 = g * 4;
            const float* src;
            float s;
            if (k0 < 16) { src = B_sh + (size_t)(n0 + tid) * 16 + k0; s = 1.f; }
            else {
                const int t = (k0 - 16) >> 4, rr = (k0 - 16) & 15;
                src = B_tasks + ((size_t)t * OK + n0 + tid) * 16 + rr;
                s = sc[t];
            }
            float4 v = __ldg(reinterpret_cast<const float4*>(src));
            bd[g * 4 + 0] = tf32f(v.x * s); bd[g * 4 + 1] = tf32f(v.y * s);
            bd[g * 4 + 2] = tf32f(v.z * s); bd[g * 4 + 3] = tf32f(v.w * s);
        }
    }
    __syncthreads();

    const int ar = wm * 64 + (lane >> 2);
    const int kk = lane & 3;
    for (int h = 0; h < 5; h++) {
        uint32_t ya[4][2][4];
#pragma unroll
        for (int i = 0; i < 4; i++)
#pragma unroll
            for (int ks = 0; ks < 2; ks++) {
                const float* bp = &Ys[(ar + i * 16) * EST + h * 16 + ks * 8 + kk];
                ya[i][ks][0] = __float_as_uint(bp[0]);
                ya[i][ks][1] = __float_as_uint(bp[8 * EST]);
                ya[i][ks][2] = __float_as_uint(bp[4]);
                ya[i][ks][3] = __float_as_uint(bp[8 * EST + 4]);
            }
        float* outh = out + (size_t)h * MTOT * OK;
#pragma unroll
        for (int j = 0; j < 8; j++) {
            uint32_t yb[2][2];
            const int bn = wn * 64 + j * 8 + (lane >> 2);
#pragma unroll
            for (int ks = 0; ks < 2; ks++) {
                const float* bp = &Bs[bn * EST + h * 16 + ks * 8 + kk];
                yb[ks][0] = __float_as_uint(bp[0]);
                yb[ks][1] = __float_as_uint(bp[4]);
            }
            const int colb = n0 + wn * 64 + j * 8 + (lane & 3) * 2;
#pragma unroll
            for (int i = 0; i < 4; i++) {
                float corr[4];
                mma_tf32_dc(corr, c[j][i], ya[i][0], yb[0]);
                mma_tf32(corr, ya[i][1], yb[1]);
                const int r0 = m0 + wm * 64 + i * 16 + (lane >> 2);
                *reinterpret_cast<float2*>(outh + (size_t)r0 * OK + colb) =
                    make_float2(corr[0], corr[1]);
                *reinterpret_cast<float2*>(outh + (size_t)(r0 + 8) * OK + colb) =
                    make_float2(corr[2], corr[3]);
            }
        }
    }
}

// ---------------------------------------------------------------------------
extern "C" void kernel_launch(void* const* d_in, const int* in_sizes, int n_in,
                              void* d_out, int out_size) {
    const float* x           = (const float*)d_in[0];
    const float* W           = (const float*)d_in[1];
    const float* b           = (const float*)d_in[2];
    const float* A_sh        = (const float*)d_in[3];
    const float* B_sh        = (const float*)d_in[4];
    const float* A_tasks     = (const float*)d_in[5];
    const float* B_tasks     = (const float*)d_in[6];
    const float* task_scales = (const float*)d_in[7];
    float* out = (float*)d_out;
    (void)in_sizes; (void)n_in; (void)out_size;

    cudaFuncSetAttribute(fused_main, cudaFuncAttributeMaxDynamicSharedMemorySize,
                         SMEM_DYN);

    prep_wt<<<OK * DK / 1024, 256>>>(W);
    lora_y_kernel<<<128, 256>>>(x, A_sh, A_tasks);
    fused_main<<<dim3(OK / BN, MTOT / BM), 256, SMEM_DYN>>>(
        b, B_sh, B_tasks, task_scales, out);
}

// round 16
// speedup vs baseline: 1.0563x; 1.0563x over previous
#include <cuda_runtime.h>
#include <cuda_bf16.h>
#include <cstdint>

// ===========================================================================
// MTLoRALinear on sm_103a — single-pass tf32 mainloop, BK=64 (R16).
// R14 (512.7us, best) reverted verbatim + streaming stores (__stcs) for the
// 671MB `out` write stream to stop L2 write-allocate from evicting the
// x tiles shared by co-scheduled N-blocks.
//   prep_wt : W fp32 -> tf32-rounded fp32
//   lora_y  : Y[M,80] = x @ concat(A_sh,A_tasks)^T (tf32) AND x -> g_xt
//   fused   : P = x@W^T single tf32 pass, BM128 BN256 BK64; epilogue: bias +
//             5 rank-16 tf32 corrections + streamed (evict-first) stores.
// ===========================================================================

namespace {
constexpr int MTOT = 32768, DK = 1024, OK = 1024;
constexpr int BM = 128, BN = 256, BK = 64;
constexpr int NCHUNK = DK / BK;           // 16
constexpr int NSTAGE = 2;
// stage layout (256B rows of 64 f32): x(32K) w(64K) = 96KB
constexpr int OFF_X = 0, OFF_W = 32768;
constexpr int STAGE_B = 98304;
constexpr int SMEM_DYN = NSTAGE * STAGE_B + 1024;   // 197632
constexpr int XST = 36;                   // lora_y smem stride
constexpr int EST = 84;                   // epilogue stride (conflict-free)
constexpr int EPI_B_OFF = 43520;          // Ys: 128*84*4=43008, Bs after
}

__device__ __align__(256) float g_xt[MTOT * DK];   // tf32-rounded x
__device__ __align__(256) float g_wt[OK * DK];     // tf32-rounded W
__device__ __align__(256) float g_Y[MTOT * 80];

// --------------------------- helpers ---------------------------------------
__device__ __forceinline__ uint32_t smem_u32(const void* p) {
    uint32_t a;
    asm("{ .reg .u64 t; cvta.to.shared.u64 t, %1; cvt.u32.u64 %0, t; }"
        : "=r"(a) : "l"(p));
    return a;
}
__device__ __forceinline__ void cp16(uint32_t dst, const void* src) {
    asm volatile("cp.async.cg.shared.global [%0], [%1], 16;"
                 :: "r"(dst), "l"(src) : "memory");
}
__device__ __forceinline__ void cp_commit() {
    asm volatile("cp.async.commit_group;" ::: "memory");
}
template <int N> __device__ __forceinline__ void cp_wait() {
    asm volatile("cp.async.wait_group %0;" :: "n"(N) : "memory");
}
__device__ __forceinline__ void ldsm4(uint32_t& r0, uint32_t& r1, uint32_t& r2,
                                      uint32_t& r3, uint32_t a) {
    asm volatile("ldmatrix.sync.aligned.m8n8.x4.shared.b16 {%0,%1,%2,%3}, [%4];"
                 : "=r"(r0), "=r"(r1), "=r"(r2), "=r"(r3) : "r"(a));
}
__device__ __forceinline__ uint32_t tf32_rna(float x) {
    uint32_t u;
    asm("cvt.rna.tf32.f32 %0, %1;" : "=r"(u) : "f"(x));
    return u;
}
__device__ __forceinline__ float tf32f(float x) {
    return __uint_as_float(tf32_rna(x));
}
__device__ __forceinline__ void mma_tf32(float* c, const uint32_t* a,
                                         const uint32_t* b) {
    asm volatile(
        "mma.sync.aligned.m16n8k8.row.col.f32.tf32.tf32.f32 "
        "{%0,%1,%2,%3}, {%4,%5,%6,%7}, {%8,%9}, {%0,%1,%2,%3};"
        : "+f"(c[0]), "+f"(c[1]), "+f"(c[2]), "+f"(c[3])
        : "r"(a[0]), "r"(a[1]), "r"(a[2]), "r"(a[3]), "r"(b[0]), "r"(b[1]));
}
__device__ __forceinline__ void mma_tf32_dc(float* d, const float* c,
                                            const uint32_t* a, const uint32_t* b) {
    asm volatile(
        "mma.sync.aligned.m16n8k8.row.col.f32.tf32.tf32.f32 "
        "{%0,%1,%2,%3}, {%4,%5,%6,%7}, {%8,%9}, {%10,%11,%12,%13};"
        : "=f"(d[0]), "=f"(d[1]), "=f"(d[2]), "=f"(d[3])
        : "r"(a[0]), "r"(a[1]), "r"(a[2]), "r"(a[3]), "r"(b[0]), "r"(b[1]),
          "f"(c[0]), "f"(c[1]), "f"(c[2]), "f"(c[3]));
}
// streaming 8B store (evict-first): keep L2 for x/W tiles
__device__ __forceinline__ void stcs2(float* p, float v0, float v1) {
    float2 v = make_float2(v0, v1);
    __stcs(reinterpret_cast<float2*>(p), v);
}
// 256B-row tile (64 f32), 16x16B chunks, XOR-8 swizzle (R14-proven).
__device__ __forceinline__ uint32_t tswz128(int row, int ch) {
    return (uint32_t)(row * 256 + ((ch ^ (row & 7)) << 4));
}

// --------------------------- prep W (tf32 round) ---------------------------
__global__ __launch_bounds__(256) void prep_wt(const float* __restrict__ W) {
    size_t i = ((size_t)blockIdx.x * 256 + threadIdx.x) * 4;
    float4 v = *reinterpret_cast<const float4*>(W + i);
    v.x = tf32f(v.x); v.y = tf32f(v.y); v.z = tf32f(v.z); v.w = tf32f(v.w);
    *reinterpret_cast<float4*>(g_wt + i) = v;
}

// ---------------- lora_y + side-write x -> tf32-rounded (R14 version) ------
__global__ __launch_bounds__(256) void lora_y_kernel(
    const float* __restrict__ x,
    const float* __restrict__ A_sh,
    const float* __restrict__ A_tasks)
{
    __shared__ float Xs[BM * XST];
    __shared__ float Ws[BM * XST];

    const int tid = threadIdx.x;
    const int lane = tid & 31, wid = tid >> 5;
    const int wm = wid >> 2, wn = wid & 3;
    const int m0 = blockIdx.x * BM;
    const int lr = tid >> 3;
    const int lc = (tid & 7) << 2;

    const float* xg = x + (size_t)(m0 + lr) * DK + lc;
    const float* ag[4];
    bool av[4];
#pragma unroll
    for (int i = 0; i < 4; i++) {
        const int r = lr + 32 * i;
        if (r < 16)      { ag[i] = A_sh + (size_t)r * DK + lc; av[i] = true; }
        else if (r < 80) { ag[i] = A_tasks + (size_t)(r - 16) * DK + lc; av[i] = true; }
        else             { ag[i] = A_sh + lc; av[i] = false; }
    }

    float4 px[4], pw[4];
    const float4 z4 = make_float4(0.f, 0.f, 0.f, 0.f);
#pragma unroll
    for (int i = 0; i < 4; i++) {
        px[i] = *reinterpret_cast<const float4*>(xg + (size_t)(32 * i) * DK);
        pw[i] = av[i] ? *reinterpret_cast<const float4*>(ag[i]) : z4;
    }

    float c[4][4][4];
#pragma unroll
    for (int i = 0; i < 4; i++)
#pragma unroll
        for (int j = 0; j < 4; j++)
#pragma unroll
            for (int q = 0; q < 4; q++) c[i][j][q] = 0.f;

    for (int kc = 0; kc < DK; kc += 32) {
        __syncthreads();
#pragma unroll
        for (int i = 0; i < 4; i++) {
            float4 xr = make_float4(tf32f(px[i].x), tf32f(px[i].y),
                                    tf32f(px[i].z), tf32f(px[i].w));
            *reinterpret_cast<float4*>(
                g_xt + (size_t)(m0 + lr + 32 * i) * DK + kc + lc) = xr;
            float* xs = &Xs[(lr + 32 * i) * XST + lc];
            xs[0] = xr.x; xs[1] = xr.y; xs[2] = xr.z; xs[3] = xr.w;
            float* ws = &Ws[(lr + 32 * i) * XST + lc];
            ws[0] = tf32f(pw[i].x); ws[1] = tf32f(pw[i].y);
            ws[2] = tf32f(pw[i].z); ws[3] = tf32f(pw[i].w);
        }
        __syncthreads();
        if (kc + 32 < DK) {
#pragma unroll
            for (int i = 0; i < 4; i++) {
                px[i] = *reinterpret_cast<const float4*>(xg + (size_t)(32 * i) * DK + kc + 32);
                pw[i] = av[i] ? *reinterpret_cast<const float4*>(ag[i] + kc + 32) : z4;
            }
        }
#pragma unroll
        for (int ks = 0; ks < 4; ks++) {
            const int ak = ks * 8 + (lane & 3);
            const int ar = wm * 64 + (lane >> 2);
            uint32_t a[4][4];
#pragma unroll
            for (int i = 0; i < 4; i++) {
                const float* base = &Xs[(ar + i * 16) * XST + ak];
                a[i][0] = __float_as_uint(base[0]);
                a[i][1] = __float_as_uint(base[8 * XST]);
                a[i][2] = __float_as_uint(base[4]);
                a[i][3] = __float_as_uint(base[8 * XST + 4]);
            }
            uint32_t b[4][2];
            const int bn = wn * 32 + (lane >> 2);
#pragma unroll
            for (int j = 0; j < 4; j++) {
                const float* base = &Ws[(bn + j * 8) * XST + ak];
                b[j][0] = __float_as_uint(base[0]);
                b[j][1] = __float_as_uint(base[4]);
            }
#pragma unroll
            for (int i = 0; i < 4; i++)
#pragma unroll
                for (int j = 0; j < 4; j++)
                    mma_tf32(c[i][j], a[i], b[j]);
        }
    }

#pragma unroll
    for (int j = 0; j < 4; j++) {
        const int colb = wn * 32 + j * 8 + (lane & 3) * 2;
        if (colb < 80) {
#pragma unroll
            for (int i = 0; i < 4; i++) {
                const int r0 = m0 + wm * 64 + i * 16 + (lane >> 2);
                *reinterpret_cast<float2*>(g_Y + (size_t)r0 * 80 + colb) =
                    make_float2(c[i][j][0], c[i][j][1]);
                *reinterpret_cast<float2*>(g_Y + (size_t)(r0 + 8) * 80 + colb) =
                    make_float2(c[i][j][2], c[i][j][3]);
            }
        }
    }
}

// --------------------------- fused main ------------------------------------
__global__ __launch_bounds__(256, 1) void fused_main(
    const float* __restrict__ bias,
    const float* __restrict__ B_sh,
    const float* __restrict__ B_tasks,
    const float* __restrict__ task_scales,
    float* __restrict__ out)
{
    extern __shared__ char dsm[];
    const uint32_t raw = smem_u32(dsm);
    const uint32_t base = (raw + 1023u) & ~1023u;
    char* sm = dsm + (base - raw);

    const int tid = threadIdx.x, wid = tid >> 5, lane = tid & 31;
    const int wm = wid >> 2, wn = wid & 3;      // 2 x 4 warps, warp tile 64x64
    const int m0 = blockIdx.y * BM, n0 = blockIdx.x * BN;

    const int trow = tid >> 3, tch = tid & 7;
    const uint32_t dsw0 = tswz128(trow, tch);
    const uint32_t dsw1 = tswz128(trow, tch + 8);
    const float* xp = g_xt + (size_t)(m0 + trow) * DK + tch * 4;
    const float* wp = g_wt + (size_t)(n0 + trow) * DK + tch * 4;

    auto issue = [&](int chunk) {
        const uint32_t sb = base + (chunk & (NSTAGE - 1)) * STAGE_B;
        const int ko = chunk * BK;
#pragma unroll
        for (int p = 0; p < 4; p++) {
            const float* s = xp + (size_t)p * 32 * DK + ko;
            cp16(sb + OFF_X + p * 8192 + dsw0, s);
            cp16(sb + OFF_X + p * 8192 + dsw1, s + 32);
        }
#pragma unroll
        for (int p = 0; p < 8; p++) {
            const float* s = wp + (size_t)p * 32 * DK + ko;
            cp16(sb + OFF_W + p * 8192 + dsw0, s);
            cp16(sb + OFF_W + p * 8192 + dsw1, s + 32);
        }
        cp_commit();
    };

    issue(0);

    float c[8][4][4];
#pragma unroll
    for (int j = 0; j < 8; j++)
#pragma unroll
        for (int i = 0; i < 4; i++)
#pragma unroll
            for (int q = 0; q < 4; q++) c[j][i][q] = 0.f;

    const int qrow = lane & 7, q = lane >> 3;
    const int a_row_off = wm * 64 + (q & 1) * 8 + qrow;       // + i*16
    const int a_ch_off = q >> 1;                              // + ks*2
    const int b_row_off = wn * 64 + ((lane >> 4) << 3) + (lane & 7);  // + jp*16
    const int b_ch_off = (lane >> 3) & 1;                     // + ks*2

    for (int it = 0; it < NCHUNK; it++) {
        cp_wait<0>();
        __syncthreads();
        if (it + 1 < NCHUNK) issue(it + 1);   // overlaps all of compute(it)
        const uint32_t sb = base + (it & (NSTAGE - 1)) * STAGE_B;
#pragma unroll
        for (int ks = 0; ks < 8; ks++) {      // 8 k8-steps per 64-K chunk
            uint32_t a[4][4];
#pragma unroll
            for (int i = 0; i < 4; i++) {
                const int row = a_row_off + i * 16;
                const uint32_t o = tswz128(row, ks * 2 + a_ch_off);
                ldsm4(a[i][0], a[i][1], a[i][2], a[i][3], sb + OFF_X + o);
            }
#pragma unroll
            for (int jp = 0; jp < 4; jp++) {
                const int row = b_row_off + jp * 16;
                const uint32_t o = tswz128(row, ks * 2 + b_ch_off);
                uint32_t b[4];
                ldsm4(b[0], b[1], b[2], b[3], sb + OFF_W + o);
#pragma unroll
                for (int jj = 0; jj < 2; jj++)
#pragma unroll
                    for (int i = 0; i < 4; i++)
                        mma_tf32(c[jp * 2 + jj][i], a[i], b + 2 * jj);
            }
        }
    }
    __syncthreads();

    // ---- bias ------------------------------------------------------------
#pragma unroll
    for (int j = 0; j < 8; j++) {
        const int col = n0 + wn * 64 + j * 8 + (lane & 3) * 2;
        const float b0 = __ldg(bias + col);
        const float b1 = __ldg(bias + col + 1);
#pragma unroll
        for (int i = 0; i < 4; i++) {
            c[j][i][0] += b0; c[j][i][1] += b1;
            c[j][i][2] += b0; c[j][i][3] += b1;
        }
    }

    // ---- epilogue: stage Y[128x80] and scaled B_all[256x80] once ----------
    float* Ys = reinterpret_cast<float*>(sm);
    float* Bs = reinterpret_cast<float*>(sm + EPI_B_OFF);
    {
        const int srow = tid >> 1, half = tid & 1;
        const float* ys = g_Y + (size_t)(m0 + srow) * 80 + half * 40;
        float* yd = Ys + srow * EST + half * 40;
#pragma unroll
        for (int g = 0; g < 10; g++) {
            float4 v = __ldg(reinterpret_cast<const float4*>(ys + g * 4));
            yd[g * 4 + 0] = tf32f(v.x); yd[g * 4 + 1] = tf32f(v.y);
            yd[g * 4 + 2] = tf32f(v.z); yd[g * 4 + 3] = tf32f(v.w);
        }
        float sc[4];
#pragma unroll
        for (int t = 0; t < 4; t++) sc[t] = __ldg(task_scales + t);
        float* bd = Bs + tid * EST;
#pragma unroll
        for (int g = 0; g < 20; g++) {
            const int k0 = g * 4;
            const float* src;
            float s;
            if (k0 < 16) { src = B_sh + (size_t)(n0 + tid) * 16 + k0; s = 1.f; }
            else {
                const int t = (k0 - 16) >> 4, rr = (k0 - 16) & 15;
                src = B_tasks + ((size_t)t * OK + n0 + tid) * 16 + rr;
                s = sc[t];
            }
            float4 v = __ldg(reinterpret_cast<const float4*>(src));
            bd[g * 4 + 0] = tf32f(v.x * s); bd[g * 4 + 1] = tf32f(v.y * s);
            bd[g * 4 + 2] = tf32f(v.z * s); bd[g * 4 + 3] = tf32f(v.w * s);
        }
    }
    __syncthreads();

    const int ar = wm * 64 + (lane >> 2);
    const int kk = lane & 3;
    for (int h = 0; h < 5; h++) {
        uint32_t ya[4][2][4];
#pragma unroll
        for (int i = 0; i < 4; i++)
#pragma unroll
            for (int ks = 0; ks < 2; ks++) {
                const float* bp = &Ys[(ar + i * 16) * EST + h * 16 + ks * 8 + kk];
                ya[i][ks][0] = __float_as_uint(bp[0]);
                ya[i][ks][1] = __float_as_uint(bp[8 * EST]);
                ya[i][ks][2] = __float_as_uint(bp[4]);
                ya[i][ks][3] = __float_as_uint(bp[8 * EST + 4]);
            }
        float* outh = out + (size_t)h * MTOT * OK;
#pragma unroll
        for (int j = 0; j < 8; j++) {
            uint32_t yb[2][2];
            const int bn = wn * 64 + j * 8 + (lane >> 2);
#pragma unroll
            for (int ks = 0; ks < 2; ks++) {
                const float* bp = &Bs[bn * EST + h * 16 + ks * 8 + kk];
                yb[ks][0] = __float_as_uint(bp[0]);
                yb[ks][1] = __float_as_uint(bp[4]);
            }
            const int colb = n0 + wn * 64 + j * 8 + (lane & 3) * 2;
#pragma unroll
            for (int i = 0; i < 4; i++) {
                float corr[4];
                mma_tf32_dc(corr, c[j][i], ya[i][0], yb[0]);
                mma_tf32(corr, ya[i][1], yb[1]);
                const int r0 = m0 + wm * 64 + i * 16 + (lane >> 2);
                stcs2(outh + (size_t)r0 * OK + colb, corr[0], corr[1]);
                stcs2(outh + (size_t)(r0 + 8) * OK + colb, corr[2], corr[3]);
            }
        }
    }
}

// ---------------------------------------------------------------------------
extern "C" void kernel_launch(void* const* d_in, const int* in_sizes, int n_in,
                              void* d_out, int out_size) {
    const float* x           = (const float*)d_in[0];
    const float* W           = (const float*)d_in[1];
    const float* b           = (const float*)d_in[2];
    const float* A_sh        = (const float*)d_in[3];
    const float* B_sh        = (const float*)d_in[4];
    const float* A_tasks     = (const float*)d_in[5];
    const float* B_tasks     = (const float*)d_in[6];
    const float* task_scales = (const float*)d_in[7];
    float* out = (float*)d_out;
    (void)in_sizes; (void)n_in; (void)out_size;

    cudaFuncSetAttribute(fused_main, cudaFuncAttributeMaxDynamicSharedMemorySize,
                         SMEM_DYN);

    prep_wt<<<OK * DK / 1024, 256>>>(W);
    lora_y_kernel<<<MTOT / BM, 256>>>(x, A_sh, A_tasks);
    fused_main<<<dim3(OK / BN, MTOT / BM), 256, SMEM_DYN>>>(
        b, B_sh, B_tasks, task_scales, out);
}

// round 17
// speedup vs baseline: 1.0883x; 1.0303x over previous
#include <cuda_runtime.h>
#include <cuda_bf16.h>
#include <cstdint>

// ===========================================================================
// MTLoRALinear on sm_103a — single-pass tf32, 2 independent CTAs/SM (R17).
// R14/R16 plateau diagnosis: one barrier-coupled CTA/SM stalls all 8 warps at
// every cp_wait/sync. Fix: BM=BN=128, 128 threads (4 warps, 64x64 tiles),
// BK=32, 3-stage x 32KB => 97KB smem/CTA, ~190 regs => 2 CTAs co-resident;
// each CTA's bubbles are covered by the peer CTA's warps.
//   prep_wt : W fp32 -> tf32-rounded fp32
//   lora_y  : Y[M,80] = x @ concat(A_sh,A_tasks)^T (tf32) AND x -> g_xt
//   fused   : P = x@W^T single tf32 pass; epilogue: bias + 5 rank-16 tf32
//             corrections + streaming stores.
// ===========================================================================

namespace {
constexpr int MTOT = 32768, DK = 1024, OK = 1024;
constexpr int BM = 128, BN = 128, BK = 32;
constexpr int NCHUNK = DK / BK;           // 32
constexpr int NSTAGE = 3;
// stage layout (128B rows of 32 f32): x(16K) w(16K) = 32KB
constexpr int OFF_X = 0, OFF_W = 16384;
constexpr int STAGE_B = 32768;
constexpr int SMEM_DYN = NSTAGE * STAGE_B + 1024;   // 99328 (2/SM: 198656)
constexpr int XST = 36;                   // lora_y smem stride
constexpr int EST = 84;                   // epilogue stride (conflict-free)
constexpr int EPI_B_OFF = 43520;          // Ys: 128*84*4=43008, Bs after
}

__device__ __align__(256) float g_xt[MTOT * DK];   // tf32-rounded x
__device__ __align__(256) float g_wt[OK * DK];     // tf32-rounded W
__device__ __align__(256) float g_Y[MTOT * 80];

// --------------------------- helpers ---------------------------------------
__device__ __forceinline__ uint32_t smem_u32(const void* p) {
    uint32_t a;
    asm("{ .reg .u64 t; cvta.to.shared.u64 t, %1; cvt.u32.u64 %0, t; }"
        : "=r"(a) : "l"(p));
    return a;
}
__device__ __forceinline__ void cp16(uint32_t dst, const void* src) {
    asm volatile("cp.async.cg.shared.global [%0], [%1], 16;"
                 :: "r"(dst), "l"(src) : "memory");
}
__device__ __forceinline__ void cp_commit() {
    asm volatile("cp.async.commit_group;" ::: "memory");
}
template <int N> __device__ __forceinline__ void cp_wait() {
    asm volatile("cp.async.wait_group %0;" :: "n"(N) : "memory");
}
__device__ __forceinline__ void ldsm4(uint32_t& r0, uint32_t& r1, uint32_t& r2,
                                      uint32_t& r3, uint32_t a) {
    asm volatile("ldmatrix.sync.aligned.m8n8.x4.shared.b16 {%0,%1,%2,%3}, [%4];"
                 : "=r"(r0), "=r"(r1), "=r"(r2), "=r"(r3) : "r"(a));
}
__device__ __forceinline__ uint32_t tf32_rna(float x) {
    uint32_t u;
    asm("cvt.rna.tf32.f32 %0, %1;" : "=r"(u) : "f"(x));
    return u;
}
__device__ __forceinline__ float tf32f(float x) {
    return __uint_as_float(tf32_rna(x));
}
__device__ __forceinline__ void mma_tf32(float* c, const uint32_t* a,
                                         const uint32_t* b) {
    asm volatile(
        "mma.sync.aligned.m16n8k8.row.col.f32.tf32.tf32.f32 "
        "{%0,%1,%2,%3}, {%4,%5,%6,%7}, {%8,%9}, {%0,%1,%2,%3};"
        : "+f"(c[0]), "+f"(c[1]), "+f"(c[2]), "+f"(c[3])
        : "r"(a[0]), "r"(a[1]), "r"(a[2]), "r"(a[3]), "r"(b[0]), "r"(b[1]));
}
__device__ __forceinline__ void mma_tf32_dc(float* d, const float* c,
                                            const uint32_t* a, const uint32_t* b) {
    asm volatile(
        "mma.sync.aligned.m16n8k8.row.col.f32.tf32.tf32.f32 "
        "{%0,%1,%2,%3}, {%4,%5,%6,%7}, {%8,%9}, {%10,%11,%12,%13};"
        : "=f"(d[0]), "=f"(d[1]), "=f"(d[2]), "=f"(d[3])
        : "r"(a[0]), "r"(a[1]), "r"(a[2]), "r"(a[3]), "r"(b[0]), "r"(b[1]),
          "f"(c[0]), "f"(c[1]), "f"(c[2]), "f"(c[3]));
}
__device__ __forceinline__ void stcs2(float* p, float v0, float v1) {
    float2 v = make_float2(v0, v1);
    __stcs(reinterpret_cast<float2*>(p), v);
}
// 128B-row tile (32 f32), 8x16B chunks, XOR-8 swizzle (R11/R14-proven).
__device__ __forceinline__ uint32_t tswz64(int row, int ch) {
    return (uint32_t)(row * 128 + ((ch ^ (row & 7)) << 4));
}

// --------------------------- prep W (tf32 round) ---------------------------
__global__ __launch_bounds__(256) void prep_wt(const float* __restrict__ W) {
    size_t i = ((size_t)blockIdx.x * 256 + threadIdx.x) * 4;
    float4 v = *reinterpret_cast<const float4*>(W + i);
    v.x = tf32f(v.x); v.y = tf32f(v.y); v.z = tf32f(v.z); v.w = tf32f(v.w);
    *reinterpret_cast<float4*>(g_wt + i) = v;
}

// ---------------- lora_y + side-write x -> tf32-rounded (R14 version) ------
__global__ __launch_bounds__(256) void lora_y_kernel(
    const float* __restrict__ x,
    const float* __restrict__ A_sh,
    const float* __restrict__ A_tasks)
{
    __shared__ float Xs[BM * XST];
    __shared__ float Ws[BM * XST];

    const int tid = threadIdx.x;
    const int lane = tid & 31, wid = tid >> 5;
    const int wm = wid >> 2, wn = wid & 3;
    const int m0 = blockIdx.x * BM;
    const int lr = tid >> 3;
    const int lc = (tid & 7) << 2;

    const float* xg = x + (size_t)(m0 + lr) * DK + lc;
    const float* ag[4];
    bool av[4];
#pragma unroll
    for (int i = 0; i < 4; i++) {
        const int r = lr + 32 * i;
        if (r < 16)      { ag[i] = A_sh + (size_t)r * DK + lc; av[i] = true; }
        else if (r < 80) { ag[i] = A_tasks + (size_t)(r - 16) * DK + lc; av[i] = true; }
        else             { ag[i] = A_sh + lc; av[i] = false; }
    }

    float4 px[4], pw[4];
    const float4 z4 = make_float4(0.f, 0.f, 0.f, 0.f);
#pragma unroll
    for (int i = 0; i < 4; i++) {
        px[i] = *reinterpret_cast<const float4*>(xg + (size_t)(32 * i) * DK);
        pw[i] = av[i] ? *reinterpret_cast<const float4*>(ag[i]) : z4;
    }

    float c[4][4][4];
#pragma unroll
    for (int i = 0; i < 4; i++)
#pragma unroll
        for (int j = 0; j < 4; j++)
#pragma unroll
            for (int q = 0; q < 4; q++) c[i][j][q] = 0.f;

    for (int kc = 0; kc < DK; kc += 32) {
        __syncthreads();
#pragma unroll
        for (int i = 0; i < 4; i++) {
            float4 xr = make_float4(tf32f(px[i].x), tf32f(px[i].y),
                                    tf32f(px[i].z), tf32f(px[i].w));
            *reinterpret_cast<float4*>(
                g_xt + (size_t)(m0 + lr + 32 * i) * DK + kc + lc) = xr;
            float* xs = &Xs[(lr + 32 * i) * XST + lc];
            xs[0] = xr.x; xs[1] = xr.y; xs[2] = xr.z; xs[3] = xr.w;
            float* ws = &Ws[(lr + 32 * i) * XST + lc];
            ws[0] = tf32f(pw[i].x); ws[1] = tf32f(pw[i].y);
            ws[2] = tf32f(pw[i].z); ws[3] = tf32f(pw[i].w);
        }
        __syncthreads();
        if (kc + 32 < DK) {
#pragma unroll
            for (int i = 0; i < 4; i++) {
                px[i] = *reinterpret_cast<const float4*>(xg + (size_t)(32 * i) * DK + kc + 32);
                pw[i] = av[i] ? *reinterpret_cast<const float4*>(ag[i] + kc + 32) : z4;
            }
        }
#pragma unroll
        for (int ks = 0; ks < 4; ks++) {
            const int ak = ks * 8 + (lane & 3);
            const int ar = wm * 64 + (lane >> 2);
            uint32_t a[4][4];
#pragma unroll
            for (int i = 0; i < 4; i++) {
                const float* base = &Xs[(ar + i * 16) * XST + ak];
                a[i][0] = __float_as_uint(base[0]);
                a[i][1] = __float_as_uint(base[8 * XST]);
                a[i][2] = __float_as_uint(base[4]);
                a[i][3] = __float_as_uint(base[8 * XST + 4]);
            }
            uint32_t b[4][2];
            const int bn = wn * 32 + (lane >> 2);
#pragma unroll
            for (int j = 0; j < 4; j++) {
                const float* base = &Ws[(bn + j * 8) * XST + ak];
                b[j][0] = __float_as_uint(base[0]);
                b[j][1] = __float_as_uint(base[4]);
            }
#pragma unroll
            for (int i = 0; i < 4; i++)
#pragma unroll
                for (int j = 0; j < 4; j++)
                    mma_tf32(c[i][j], a[i], b[j]);
        }
    }

#pragma unroll
    for (int j = 0; j < 4; j++) {
        const int colb = wn * 32 + j * 8 + (lane & 3) * 2;
        if (colb < 80) {
#pragma unroll
            for (int i = 0; i < 4; i++) {
                const int r0 = m0 + wm * 64 + i * 16 + (lane >> 2);
                *reinterpret_cast<float2*>(g_Y + (size_t)r0 * 80 + colb) =
                    make_float2(c[i][j][0], c[i][j][1]);
                *reinterpret_cast<float2*>(g_Y + (size_t)(r0 + 8) * 80 + colb) =
                    make_float2(c[i][j][2], c[i][j][3]);
            }
        }
    }
}

// ------------------- fused main (128 threads, 2 CTAs/SM) -------------------
__global__ __launch_bounds__(128, 2) void fused_main(
    const float* __restrict__ bias,
    const float* __restrict__ B_sh,
    const float* __restrict__ B_tasks,
    const float* __restrict__ task_scales,
    float* __restrict__ out)
{
    extern __shared__ char dsm[];
    const uint32_t raw = smem_u32(dsm);
    const uint32_t base = (raw + 1023u) & ~1023u;
    char* sm = dsm + (base - raw);

    const int tid = threadIdx.x, wid = tid >> 5, lane = tid & 31;
    const int wm = wid >> 1, wn = wid & 1;      // 2 x 2 warps, warp tile 64x64
    const int m0 = blockIdx.y * BM, n0 = blockIdx.x * BN;

    // ---- cp.async: thread -> row tid>>3 (0..15, 8 pages of 16), chunk tid&7
    const int trow = tid >> 3, tch = tid & 7;
    const uint32_t dsw = tswz64(trow, tch);     // swz(row+16p) = swz(row)+p*2048
    const float* xp = g_xt + (size_t)(m0 + trow) * DK + tch * 4;
    const float* wp = g_wt + (size_t)(n0 + trow) * DK + tch * 4;

    auto issue = [&](int chunk) {
        int s = chunk % NSTAGE;
        const uint32_t sb = base + s * STAGE_B;
        const int ko = chunk * BK;
#pragma unroll
        for (int p = 0; p < 8; p++) {
            cp16(sb + OFF_X + p * 2048 + dsw, xp + (size_t)p * 16 * DK + ko);
            cp16(sb + OFF_W + p * 2048 + dsw, wp + (size_t)p * 16 * DK + ko);
        }
        cp_commit();
    };

    issue(0); issue(1);

    float c[8][4][4];
#pragma unroll
    for (int j = 0; j < 8; j++)
#pragma unroll
        for (int i = 0; i < 4; i++)
#pragma unroll
            for (int q = 0; q < 4; q++) c[j][i][q] = 0.f;

    const int qrow = lane & 7, q = lane >> 3;
    const int a_row_off = wm * 64 + (q & 1) * 8 + qrow;       // + i*16
    const int a_ch_off = q >> 1;                              // + ks*2
    const int b_row_off = wn * 64 + ((lane >> 4) << 3) + (lane & 7);  // + jp*16
    const int b_ch_off = (lane >> 3) & 1;                     // + ks*2

    for (int it = 0; it < NCHUNK; it++) {
        cp_wait<1>();
        __syncthreads();
        if (it + 2 < NCHUNK) issue(it + 2);   // overlaps compute(it)
        else cp_commit();
        const uint32_t sb = base + (it % NSTAGE) * STAGE_B;
#pragma unroll
        for (int ks = 0; ks < 4; ks++) {      // 4 k8-steps per 32-K chunk
            uint32_t a[4][4];
#pragma unroll
            for (int i = 0; i < 4; i++) {
                const int row = a_row_off + i * 16;
                const uint32_t o = tswz64(row, ks * 2 + a_ch_off);
                ldsm4(a[i][0], a[i][1], a[i][2], a[i][3], sb + OFF_X + o);
            }
#pragma unroll
            for (int jp = 0; jp < 4; jp++) {
                const int row = b_row_off + jp * 16;
                const uint32_t o = tswz64(row, ks * 2 + b_ch_off);
                uint32_t b[4];
                ldsm4(b[0], b[1], b[2], b[3], sb + OFF_W + o);
#pragma unroll
                for (int jj = 0; jj < 2; jj++)
#pragma unroll
                    for (int i = 0; i < 4; i++)
                        mma_tf32(c[jp * 2 + jj][i], a[i], b + 2 * jj);
            }
        }
    }
    cp_wait<0>();
    __syncthreads();

    // ---- bias ------------------------------------------------------------
#pragma unroll
    for (int j = 0; j < 8; j++) {
        const int col = n0 + wn * 64 + j * 8 + (lane & 3) * 2;
        const float b0 = __ldg(bias + col);
        const float b1 = __ldg(bias + col + 1);
#pragma unroll
        for (int i = 0; i < 4; i++) {
            c[j][i][0] += b0; c[j][i][1] += b1;
            c[j][i][2] += b0; c[j][i][3] += b1;
        }
    }

    // ---- epilogue: stage Y[128x80] and scaled B_all[128x80] once ----------
    float* Ys = reinterpret_cast<float*>(sm);
    float* Bs = reinterpret_cast<float*>(sm + EPI_B_OFF);
    {
        const int srow = tid;                // one thread per row (128 rows)
        const float* ys = g_Y + (size_t)(m0 + srow) * 80;
        float* yd = Ys + srow * EST;
#pragma unroll
        for (int g = 0; g < 20; g++) {
            float4 v = __ldg(reinterpret_cast<const float4*>(ys + g * 4));
            yd[g * 4 + 0] = tf32f(v.x); yd[g * 4 + 1] = tf32f(v.y);
            yd[g * 4 + 2] = tf32f(v.z); yd[g * 4 + 3] = tf32f(v.w);
        }
        float sc[4];
#pragma unroll
        for (int t = 0; t < 4; t++) sc[t] = __ldg(task_scales + t);
        float* bd = Bs + srow * EST;
#pragma unroll
        for (int g = 0; g < 20; g++) {
            const int k0 = g * 4;
            const float* src;
            float s;
            if (k0 < 16) { src = B_sh + (size_t)(n0 + srow) * 16 + k0; s = 1.f; }
            else {
                const int t = (k0 - 16) >> 4, rr = (k0 - 16) & 15;
                src = B_tasks + ((size_t)t * OK + n0 + srow) * 16 + rr;
                s = sc[t];
            }
            float4 v = __ldg(reinterpret_cast<const float4*>(src));
            bd[g * 4 + 0] = tf32f(v.x * s); bd[g * 4 + 1] = tf32f(v.y * s);
            bd[g * 4 + 2] = tf32f(v.z * s); bd[g * 4 + 3] = tf32f(v.w * s);
        }
    }
    __syncthreads();

    const int ar = wm * 64 + (lane >> 2);
    const int kk = lane & 3;
    for (int h = 0; h < 5; h++) {
        uint32_t ya[4][2][4];
#pragma unroll
        for (int i = 0; i < 4; i++)
#pragma unroll
            for (int ks = 0; ks < 2; ks++) {
                const float* bp = &Ys[(ar + i * 16) * EST + h * 16 + ks * 8 + kk];
                ya[i][ks][0] = __float_as_uint(bp[0]);
                ya[i][ks][1] = __float_as_uint(bp[8 * EST]);
                ya[i][ks][2] = __float_as_uint(bp[4]);
                ya[i][ks][3] = __float_as_uint(bp[8 * EST + 4]);
            }
        float* outh = out + (size_t)h * MTOT * OK;
#pragma unroll
        for (int j = 0; j < 8; j++) {
            uint32_t yb[2][2];
            const int bn = wn * 64 + j * 8 + (lane >> 2);
#pragma unroll
            for (int ks = 0; ks < 2; ks++) {
                const float* bp = &Bs[bn * EST + h * 16 + ks * 8 + kk];
                yb[ks][0] = __float_as_uint(bp[0]);
                yb[ks][1] = __float_as_uint(bp[4]);
            }
            const int colb = n0 + wn * 64 + j * 8 + (lane & 3) * 2;
#pragma unroll
            for (int i = 0; i < 4; i++) {
                float corr[4];
                mma_tf32_dc(corr, c[j][i], ya[i][0], yb[0]);
                mma_tf32(corr, ya[i][1], yb[1]);
                const int r0 = m0 + wm * 64 + i * 16 + (lane >> 2);
                stcs2(outh + (size_t)r0 * OK + colb, corr[0], corr[1]);
                stcs2(outh + (size_t)(r0 + 8) * OK + colb, corr[2], corr[3]);
            }
        }
    }
}

// ---------------------------------------------------------------------------
extern "C" void kernel_launch(void* const* d_in, const int* in_sizes, int n_in,
                              void* d_out, int out_size) {
    const float* x           = (const float*)d_in[0];
    const float* W           = (const float*)d_in[1];
    const float* b           = (const float*)d_in[2];
    const float* A_sh        = (const float*)d_in[3];
    const float* B_sh        = (const float*)d_in[4];
    const float* A_tasks     = (const float*)d_in[5];
    const float* B_tasks     = (const float*)d_in[6];
    const float* task_scales = (const float*)d_in[7];
    float* out = (float*)d_out;
    (void)in_sizes; (void)n_in; (void)out_size;

    cudaFuncSetAttribute(fused_main, cudaFuncAttributeMaxDynamicSharedMemorySize,
                         SMEM_DYN);

    prep_wt<<<OK * DK / 1024, 256>>>(W);
    lora_y_kernel<<<MTOT / BM, 256>>>(x, A_sh, A_tasks);
    fused_main<<<dim3(OK / BN, MTOT / BM), 128, SMEM_DYN>>>(
        b, B_sh, B_tasks, task_scales, out);
}